// round 8
// baseline (speedup 1.0000x reference)
#include <cuda_runtime.h>

typedef unsigned long long u64;

#define SEQ   256
#define LAB   128
#define BATCH 8192
#define NF    8
#define HD    64
#define G3    192
#define NTHR  256          // 8 warps: 4 row-groups x 2 unit-halves
#define TB    32           // rows per block (4 groups x 8 rows)
#define NBLK  (BATCH / TB) // 256
#define HS    12           // h_T k-row stride (floats): 48B, 16B-aligned

// ---- SMEM layout (float offsets) ----
#define OFF_WIH  0                       // [8 k][192]  (gate*64 + unit)
#define OFF_WHH  1536                    // [64 k][192]
#define OFF_BIAS 13824                   // [4][64] : r, z, n_i, n_h
#define OFF_WOUT 14080                   // [64 k][4 o][2] pairs (Wout[o][k],Wout[o+4][k])
#define OFF_BOUT 14592                   // [4][2]
#define OFF_HT   14608                   // [4 g][2 buf][64 k][HS]
#define OFF_XT   (OFF_HT + 4*2*64*HS)    // [4 g][2 buf][8 feat][8 row]
#define SMEM_FLOATS (OFF_XT + 4*2*64)
#define SMEM_BYTES  (SMEM_FLOATS * 4)

__device__ __forceinline__ u64 f2fma(u64 a, u64 b, u64 c) {
    u64 d; asm("fma.rn.f32x2 %0,%1,%2,%3;" : "=l"(d) : "l"(a), "l"(b), "l"(c)); return d;
}
__device__ __forceinline__ u64 dup2(float v) {
    u64 d; asm("mov.b64 %0,{%1,%1};" : "=l"(d) : "f"(v)); return d;
}
__device__ __forceinline__ u64 pack2(float a, float b) {
    u64 d; asm("mov.b64 %0,{%1,%2};" : "=l"(d) : "f"(a), "f"(b)); return d;
}
__device__ __forceinline__ void unpk(u64 v, float& a, float& b) {
    asm("mov.b64 {%0,%1},%2;" : "=f"(a), "=f"(b) : "l"(v));
}
__device__ __forceinline__ float tanha(float x) {
    float y; asm("tanh.approx.f32 %0,%1;" : "=f"(y) : "f"(x)); return y;
}
__device__ __forceinline__ float sigt(float x) { return fmaf(0.5f, tanha(0.5f * x), 0.5f); }
__device__ __forceinline__ void pair_bar(int g) {
    asm volatile("bar.sync %0, 64;" :: "r"(1 + g) : "memory");
}

// One GRU step: warp handles 8 rows x 32 units (its half). Rows packed in f32x2.
__device__ __forceinline__ void gru_step(
    const float* __restrict__ wih,   // [8][192]
    const float* __restrict__ whh,   // [64][192]
    u64 br, u64 bz, u64 bni, u64 bnh,
    const float* __restrict__ xt,    // x_T[feat][8 rows]
    const float* __restrict__ hc,    // h_T cur  [k][HS]
    float*       __restrict__ hn,    // h_T next [k][HS]
    float hr[8],                     // this lane's unit: old h for 8 rows (regs)
    int u)
{
    u64 Ar[4], Az[4], An[4], Ah[4];
    #pragma unroll
    for (int rp = 0; rp < 4; rp++) { Ar[rp] = br; Az[rp] = bz; An[rp] = bni; Ah[rp] = bnh; }

    // ---- input GEMM (k = 0..7) ----
    #pragma unroll
    for (int kf = 0; kf < NF; kf++) {
        const float* w = wih + kf * G3 + u;
        u64 wr = dup2(w[0]), wz = dup2(w[64]), wn = dup2(w[128]);
        ulonglong2 x01 = *(const ulonglong2*)(xt + kf * 8);
        ulonglong2 x23 = *(const ulonglong2*)(xt + kf * 8 + 4);
        u64 xp0 = x01.x, xp1 = x01.y, xp2 = x23.x, xp3 = x23.y;
        Ar[0] = f2fma(xp0, wr, Ar[0]); Az[0] = f2fma(xp0, wz, Az[0]); An[0] = f2fma(xp0, wn, An[0]);
        Ar[1] = f2fma(xp1, wr, Ar[1]); Az[1] = f2fma(xp1, wz, Az[1]); An[1] = f2fma(xp1, wn, An[1]);
        Ar[2] = f2fma(xp2, wr, Ar[2]); Az[2] = f2fma(xp2, wz, Az[2]); An[2] = f2fma(xp2, wn, An[2]);
        Ar[3] = f2fma(xp3, wr, Ar[3]); Az[3] = f2fma(xp3, wz, Az[3]); An[3] = f2fma(xp3, wn, An[3]);
    }

    // ---- recurrent GEMM (k = 0..63) ----
    #pragma unroll 4
    for (int k = 0; k < HD; k++) {
        const float* w = whh + k * G3 + u;
        u64 wr = dup2(w[0]), wz = dup2(w[64]), wn = dup2(w[128]);
        ulonglong2 h01 = *(const ulonglong2*)(hc + k * HS);
        ulonglong2 h23 = *(const ulonglong2*)(hc + k * HS + 4);
        u64 hp0 = h01.x, hp1 = h01.y, hp2 = h23.x, hp3 = h23.y;
        Ar[0] = f2fma(hp0, wr, Ar[0]); Az[0] = f2fma(hp0, wz, Az[0]); Ah[0] = f2fma(hp0, wn, Ah[0]);
        Ar[1] = f2fma(hp1, wr, Ar[1]); Az[1] = f2fma(hp1, wz, Az[1]); Ah[1] = f2fma(hp1, wn, Ah[1]);
        Ar[2] = f2fma(hp2, wr, Ar[2]); Az[2] = f2fma(hp2, wz, Az[2]); Ah[2] = f2fma(hp2, wn, Ah[2]);
        Ar[3] = f2fma(hp3, wr, Ar[3]); Az[3] = f2fma(hp3, wz, Az[3]); Ah[3] = f2fma(hp3, wn, Ah[3]);
    }

    // ---- gates + h update (lane owns unit u, 8 rows; old h in regs) ----
    #pragma unroll
    for (int rp = 0; rp < 4; rp++) {
        float r0, r1, z0, z1, i0, i1, g0, g1;
        unpk(Ar[rp], r0, r1); unpk(Az[rp], z0, z1);
        unpk(An[rp], i0, i1); unpk(Ah[rp], g0, g1);
        float R0 = sigt(r0), R1 = sigt(r1);
        float Z0 = sigt(z0), Z1 = sigt(z1);
        float N0 = tanha(fmaf(R0, g0, i0));
        float N1 = tanha(fmaf(R1, g1, i1));
        hr[2 * rp]     = fmaf(Z0, hr[2 * rp]     - N0, N0);
        hr[2 * rp + 1] = fmaf(Z1, hr[2 * rp + 1] - N1, N1);
    }
    // write h_T[u][0..7] (scalars; read next step as row-pairs)
    ulonglong2 s0, s1;
    s0.x = pack2(hr[0], hr[1]); s0.y = pack2(hr[2], hr[3]);
    s1.x = pack2(hr[4], hr[5]); s1.y = pack2(hr[6], hr[7]);
    *(ulonglong2*)(hn + u * HS)     = s0;
    *(ulonglong2*)(hn + u * HS + 4) = s1;
}

__device__ __forceinline__ void load_weights(
    float* smem,
    const float* __restrict__ Wih, const float* __restrict__ Whh,
    const float* __restrict__ bih, const float* __restrict__ bhh, int tid)
{
    for (int i = tid; i < NF * G3; i += NTHR) {          // wih[k][j] = Wih[j][k]
        int k = i / G3, j = i % G3;
        smem[OFF_WIH + i] = Wih[j * NF + k];
    }
    for (int i = tid; i < HD * G3; i += NTHR) {
        int k = i / G3, j = i % G3;
        smem[OFF_WHH + i] = Whh[j * HD + k];
    }
    if (tid < HD) {
        smem[OFF_BIAS + tid]       = bih[tid]       + bhh[tid];
        smem[OFF_BIAS + 64 + tid]  = bih[64 + tid]  + bhh[64 + tid];
        smem[OFF_BIAS + 128 + tid] = bih[128 + tid];
        smem[OFF_BIAS + 192 + tid] = bhh[128 + tid];
    }
}

__global__ __launch_bounds__(NTHR, 2)
void seq2seq_gru_kernel(const float* __restrict__ x,
                        const float* __restrict__ xy,
                        const float* __restrict__ eWih, const float* __restrict__ eWhh,
                        const float* __restrict__ ebih, const float* __restrict__ ebhh,
                        const float* __restrict__ dWih, const float* __restrict__ dWhh,
                        const float* __restrict__ dbih, const float* __restrict__ dbhh,
                        const float* __restrict__ Wout, const float* __restrict__ bout,
                        float* __restrict__ out)
{
    extern __shared__ float smem[];
    const int tid  = threadIdx.x;
    const int lane = tid & 31;
    const int warp = tid >> 5;
    const int g    = warp >> 1;          // row group 0..3
    const int uh   = warp & 1;           // unit half
    const int u    = uh * 32 + lane;     // this lane's unit 0..63
    const int rowb = blockIdx.x * TB + g * 8;

    const float* wih = smem + OFF_WIH;
    const float* whh = smem + OFF_WHH;
    float* ht = smem + OFF_HT + g * (2 * 64 * HS);   // + buf*768
    float* xt = smem + OFF_XT + g * 128;             // + buf*64

    // ---- init: encoder weights, out-proj, zero h, stage x[0] ----
    load_weights(smem, eWih, eWhh, ebih, ebhh, tid);
    for (int i = tid; i < HD * 8; i += NTHR) {       // wout pairs
        int k = i >> 3, rem = i & 7, o = rem >> 1, s = rem & 1;
        smem[OFF_WOUT + i] = Wout[(o + 4 * s) * HD + k];
    }
    if (tid < 8) { int o = tid >> 1, s = tid & 1; smem[OFF_BOUT + tid] = bout[o + 4 * s]; }
    for (int i = tid; i < 4 * 2 * 64 * HS; i += NTHR) smem[OFF_HT + i] = 0.0f;
    if (uh == 0 && lane < 16) {                      // stage x[0] transposed into buf0
        float4 v = ((const float4*)(x + (size_t)rowb * NF))[lane];
        int i0 = lane * 4;
        xt[((i0 + 0) & 7) * 8 + ((i0 + 0) >> 3)] = v.x;
        xt[((i0 + 1) & 7) * 8 + ((i0 + 1) >> 3)] = v.y;
        xt[((i0 + 2) & 7) * 8 + ((i0 + 2) >> 3)] = v.z;
        xt[((i0 + 3) & 7) * 8 + ((i0 + 3) >> 3)] = v.w;
    }
    __syncthreads();

    float hr[8];
    #pragma unroll
    for (int r = 0; r < 8; r++) hr[r] = 0.0f;

    u64 br  = dup2(smem[OFF_BIAS + u]);
    u64 bz  = dup2(smem[OFF_BIAS + 64 + u]);
    u64 bni = dup2(smem[OFF_BIAS + 128 + u]);
    u64 bnh = dup2(smem[OFF_BIAS + 192 + u]);

    // =========================== ENCODER ===========================
    for (int t = 0; t < SEQ; t++) {
        const bool st = (uh == 0) && (lane < 16) && (t + 1 < SEQ);
        float4 nx;
        if (st) nx = ((const float4*)(x + ((size_t)(t + 1) * BATCH + rowb) * NF))[lane];
        gru_step(wih, whh, br, bz, bni, bnh,
                 xt + (t & 1) * 64,
                 ht + (t & 1) * 768, ht + ((t + 1) & 1) * 768,
                 hr, u);
        if (st) {
            float* xn = xt + ((t + 1) & 1) * 64;
            int i0 = lane * 4;
            xn[((i0 + 0) & 7) * 8 + ((i0 + 0) >> 3)] = nx.x;
            xn[((i0 + 1) & 7) * 8 + ((i0 + 1) >> 3)] = nx.y;
            xn[((i0 + 2) & 7) * 8 + ((i0 + 2) >> 3)] = nx.z;
            xn[((i0 + 3) & 7) * 8 + ((i0 + 3) >> 3)] = nx.w;
        }
        pair_bar(g);   // h(next) + x(next) visible to partner warp
    }

    // ---- phase swap: decoder weights, stage xy[0] ----
    __syncthreads();
    load_weights(smem, dWih, dWhh, dbih, dbhh, tid);
    if (uh == 0 && lane < 16) {                      // stage xy[0] into buf0
        float4 v = ((const float4*)(xy + (size_t)rowb * NF))[lane];
        int i0 = lane * 4;
        xt[((i0 + 0) & 7) * 8 + ((i0 + 0) >> 3)] = v.x;
        xt[((i0 + 1) & 7) * 8 + ((i0 + 1) >> 3)] = v.y;
        xt[((i0 + 2) & 7) * 8 + ((i0 + 2) >> 3)] = v.z;
        xt[((i0 + 3) & 7) * 8 + ((i0 + 3) >> 3)] = v.w;
    }
    __syncthreads();

    br  = dup2(smem[OFF_BIAS + u]);
    bz  = dup2(smem[OFF_BIAS + 64 + u]);
    bni = dup2(smem[OFF_BIAS + 128 + u]);
    bnh = dup2(smem[OFF_BIAS + 192 + u]);

    // =========================== DECODER ===========================
    // out-proj: lanes 0..15: row = lane>>1, o2 = lane&1 -> o = uh*2 + o2 (and o+4)
    const int orow = lane >> 1;
    const int oo   = uh * 2 + (lane & 1);
    const u64 bop  = ((const u64*)(smem + OFF_BOUT))[oo];
    const u64* woutq = (const u64*)(smem + OFF_WOUT) + oo;   // stride 4 u64 per k

    for (int t = 0; t < LAB; t++) {
        gru_step(wih, whh, br, bz, bni, bnh,
                 xt + (t & 1) * 64,
                 ht + (t & 1) * 768, ht + ((t + 1) & 1) * 768,
                 hr, u);
        pair_bar(g);   // full h(next) visible

        if (lane < 16) {
            const float* hn = ht + ((t + 1) & 1) * 768;
            u64 acc = bop;
            #pragma unroll 8
            for (int k = 0; k < HD; k++)
                acc = f2fma(dup2(hn[k * HS + orow]), woutq[k * 4], acc);
            float oa, ob; unpk(acc, oa, ob);

            float* og = out + ((size_t)t * BATCH + rowb + orow) * NF;
            og[oo]     = oa;
            og[oo + 4] = ob;

            if (t + 1 < LAB) {
                float* xn = xt + ((t + 1) & 1) * 64;
                xn[oo * 8 + orow]       = oa;
                xn[(oo + 4) * 8 + orow] = ob;
            }
        }
        pair_bar(g);   // feedback x(next) visible
    }
}

extern "C" void kernel_launch(void* const* d_in, const int* in_sizes, int n_in,
                              void* d_out, int out_size) {
    (void)in_sizes; (void)n_in; (void)out_size;
    const float* x     = (const float*)d_in[0];
    const float* xy    = (const float*)d_in[1];
    const float* eWih  = (const float*)d_in[2];
    const float* eWhh  = (const float*)d_in[3];
    const float* ebih  = (const float*)d_in[4];
    const float* ebhh  = (const float*)d_in[5];
    const float* dWih  = (const float*)d_in[6];
    const float* dWhh  = (const float*)d_in[7];
    const float* dbih  = (const float*)d_in[8];
    const float* dbhh  = (const float*)d_in[9];
    const float* Wout  = (const float*)d_in[10];
    const float* bout  = (const float*)d_in[11];
    float* out = (float*)d_out;

    cudaFuncSetAttribute(seq2seq_gru_kernel,
                         cudaFuncAttributeMaxDynamicSharedMemorySize, SMEM_BYTES);
    seq2seq_gru_kernel<<<NBLK, NTHR, SMEM_BYTES>>>(
        x, xy, eWih, eWhh, ebih, ebhh, dWih, dWhh, dbih, dbhh, Wout, bout, out);
}

// round 10
// speedup vs baseline: 1.9757x; 1.9757x over previous
#include <cuda_runtime.h>
#include <cuda_fp16.h>

typedef unsigned int u32;

#define SEQ   256
#define LAB   128
#define BATCH 8192
#define ROWS  64
#define NBLK  (BATCH / ROWS)   // 128
#define NTHR  256
#define KP    88               // A/B k-stride in fp16 (176B rows: conflict-free ldmatrix)
#define RB    176
#define KC    5                // 5 k-chunks of 16 (K=80 used: 64 h + 8 x + 1 bias + 7 pad)

// ---- SMEM byte offsets ----
#define SA_HI 0                // A_hi [64][88] fp16
#define SA_LO 11264            // A_lo
#define SB    22528            // B scratch [256][88] fp16 (init/phase only)
#define SWOUT 67584            // [64][8] f32
#define SBOUT 69632            // [8] f32
#define STOT  69696

static __device__ __forceinline__ u32 sptr(const void* p) {
    return (u32)__cvta_generic_to_shared(p);
}
static __device__ __forceinline__ void ldm4(u32* r, u32 a) {
    asm volatile("ldmatrix.sync.aligned.m8n8.x4.shared.b16 {%0,%1,%2,%3},[%4];"
        : "=r"(r[0]), "=r"(r[1]), "=r"(r[2]), "=r"(r[3]) : "r"(a));
}
static __device__ __forceinline__ void ldm2(u32* r, u32 a) {
    asm volatile("ldmatrix.sync.aligned.m8n8.x2.shared.b16 {%0,%1},[%2];"
        : "=r"(r[0]), "=r"(r[1]) : "r"(a));
}
static __device__ __forceinline__ void mmaop(float* d, const u32* a, const u32* b) {
    asm volatile("mma.sync.aligned.m16n8k16.row.col.f32.f16.f16.f32 "
        "{%0,%1,%2,%3},{%4,%5,%6,%7},{%8,%9},{%0,%1,%2,%3};"
        : "+f"(d[0]), "+f"(d[1]), "+f"(d[2]), "+f"(d[3])
        : "r"(a[0]), "r"(a[1]), "r"(a[2]), "r"(a[3]), "r"(b[0]), "r"(b[1]));
}
static __device__ __forceinline__ float tanha(float x) {
    float y; asm("tanh.approx.f32 %0,%1;" : "=f"(y) : "f"(x)); return y;
}
static __device__ __forceinline__ float sigt(float x) { return fmaf(0.5f, tanha(0.5f * x), 0.5f); }

// Build B[n][k] (one term: 0=hi, 1=lo) in SMEM scratch. Gate rows: r 0-63, z 64-127 (cols 0-127
// of D), ni 128-191, nh 192-255. k: 0-63 Whh, 64-71 Wih, 72 bias, 73+ zero.
static __device__ void build_B(half* Bs,
                               const float* __restrict__ Wih, const float* __restrict__ Whh,
                               const float* __restrict__ bih, const float* __restrict__ bhh,
                               int term, int tid) {
    for (int i = tid; i < 256 * KP; i += NTHR) {
        int n = i / KP, k = i % KP;
        float v = 0.0f;
        if (k < 64) {
            if (n < 128) v = Whh[n * 64 + k];               // r,z: recurrent
            else if (n >= 192) v = Whh[(n - 64) * 64 + k];  // nh: Whh rows 128-191
        } else if (k < 72) {
            if (n < 192) v = Wih[n * 8 + (k - 64)];         // r,z,ni: input
        } else if (k == 72) {
            if (n < 128) v = bih[n] + bhh[n];
            else if (n < 192) v = bih[n];
            else v = bhh[n - 64];
        }
        half h = __float2half_rn(v);
        if (term) h = __float2half_rn(v - __half2float(h));
        Bs[i] = h;
    }
}

// Each warp loads its resident B fragments: q-th n-tile = warp + 8q (units warp*8..+7 per gate).
static __device__ __forceinline__ void load_frags(const half* Bs, int warp, int lane,
                                                  u32 bf[4][KC][2]) {
    u32 base = sptr(Bs) + (u32)((lane & 7) * RB + ((lane >> 3) & 1) * 16);
    #pragma unroll
    for (int q = 0; q < 4; q++) {
        u32 bq = base + (u32)((warp + 8 * q) * 8 * RB);
        #pragma unroll
        for (int kc = 0; kc < KC; kc++) ldm2(bf[q][kc], bq + kc * 32);
    }
}

static __device__ __forceinline__ void gemm_step(const u32 aHi[4], const u32 aLo[4],
                                                 const u32 Bh[4][KC][2], const u32 Bl[4][KC][2],
                                                 float D[4][4][4]) {
    #pragma unroll
    for (int mt = 0; mt < 4; mt++)
        #pragma unroll
        for (int q = 0; q < 4; q++)
            #pragma unroll
            for (int e = 0; e < 4; e++) D[mt][q][e] = 0.0f;
    #pragma unroll
    for (int kc = 0; kc < KC; kc++) {
        u32 ah[4][4], al[4][4];
        #pragma unroll
        for (int mt = 0; mt < 4; mt++) {
            ldm4(ah[mt], aHi[mt] + kc * 32);
            ldm4(al[mt], aLo[mt] + kc * 32);
        }
        #pragma unroll
        for (int mt = 0; mt < 4; mt++)
            #pragma unroll
            for (int q = 0; q < 4; q++) {
                mmaop(D[mt][q], ah[mt], Bh[q][kc]);
                mmaop(D[mt][q], al[mt], Bh[q][kc]);
                mmaop(D[mt][q], ah[mt], Bl[q][kc]);
            }
    }
}

// Gates in registers; write h' (hi/lo fp16) back into A for next step.
static __device__ __forceinline__ void epi(half* Ahi, half* Alo, int warp, int lane,
                                           float D[4][4][4], float hold[4][4]) {
    const int r0 = lane >> 2;
    const int c0 = warp * 8 + 2 * (lane & 3);
    #pragma unroll
    for (int mt = 0; mt < 4; mt++) {
        float h[4];
        #pragma unroll
        for (int j = 0; j < 4; j++) {
            float R = sigt(D[mt][0][j]);
            float Z = sigt(D[mt][1][j]);
            float N = tanha(fmaf(R, D[mt][3][j], D[mt][2][j]));
            h[j] = fmaf(Z, hold[mt][j] - N, N);
            hold[mt][j] = h[j];
        }
        int ra = mt * 16 + r0, rb = ra + 8;
        half2 h2a = __floats2half2_rn(h[0], h[1]);
        half2 l2a = __floats2half2_rn(h[0] - __low2float(h2a), h[1] - __high2float(h2a));
        half2 h2b = __floats2half2_rn(h[2], h[3]);
        half2 l2b = __floats2half2_rn(h[2] - __low2float(h2b), h[3] - __high2float(h2b));
        *(half2*)(Ahi + ra * KP + c0) = h2a;
        *(half2*)(Alo + ra * KP + c0) = l2a;
        *(half2*)(Ahi + rb * KP + c0) = h2b;
        *(half2*)(Alo + rb * KP + c0) = l2b;
    }
}

static __device__ __forceinline__ void stage_x(half* Ahi, half* Alo, int row, const float* v) {
    #pragma unroll
    for (int j = 0; j < 4; j++) {
        float a = v[2 * j], b = v[2 * j + 1];
        half2 h2 = __floats2half2_rn(a, b);
        half2 l2 = __floats2half2_rn(a - __low2float(h2), b - __high2float(h2));
        *(half2*)(Ahi + row * KP + 64 + 2 * j) = h2;
        *(half2*)(Alo + row * KP + 64 + 2 * j) = l2;
    }
}

__global__ __launch_bounds__(NTHR, 1)
void seq2seq_mma_kernel(const float* __restrict__ x,
                        const float* __restrict__ xy,
                        const float* __restrict__ eWih, const float* __restrict__ eWhh,
                        const float* __restrict__ ebih, const float* __restrict__ ebhh,
                        const float* __restrict__ dWih, const float* __restrict__ dWhh,
                        const float* __restrict__ dbih, const float* __restrict__ dbhh,
                        const float* __restrict__ Wout, const float* __restrict__ bout,
                        float* __restrict__ out)
{
    extern __shared__ char smem[];
    half*  Ahi = (half*)(smem + SA_HI);
    half*  Alo = (half*)(smem + SA_LO);
    half*  Bs  = (half*)(smem + SB);
    float* wo  = (float*)(smem + SWOUT);
    float* bo  = (float*)(smem + SBOUT);

    const int tid  = threadIdx.x;
    const int lane = tid & 31;
    const int warp = tid >> 5;
    const int rowb = blockIdx.x * ROWS;

    // ---- zero A (h=0 + pads), wout, bias column, stage x[0] ----
    for (int i = tid; i < 22528 / 16; i += NTHR) ((uint4*)smem)[i] = make_uint4(0, 0, 0, 0);
    for (int i = tid; i < 512; i += NTHR) { int k = i >> 3, o = i & 7; wo[i] = Wout[o * 64 + k]; }
    if (tid < 8) bo[tid] = bout[tid];
    __syncthreads();
    if (tid < ROWS) {
        Ahi[tid * KP + 72] = __float2half(1.0f);      // bias lane (lo stays 0)
        const float4* p = (const float4*)(x + ((size_t)rowb + tid) * 8);
        float4 a = p[0], b = p[1];
        float v[8] = {a.x, a.y, a.z, a.w, b.x, b.y, b.z, b.w};
        stage_x(Ahi, Alo, tid, v);
    }

    // ---- encoder B fragments (registers) ----
    u32 Bh[4][KC][2], Bl[4][KC][2];
    __syncthreads();
    build_B(Bs, eWih, eWhh, ebih, ebhh, 0, tid);  __syncthreads();
    load_frags(Bs, warp, lane, Bh);               __syncthreads();
    build_B(Bs, eWih, eWhh, ebih, ebhh, 1, tid);  __syncthreads();
    load_frags(Bs, warp, lane, Bl);               __syncthreads();

    // A fragment base addresses (per mt; +kc*32 per chunk)
    u32 aHi[4], aLo[4];
    {
        int t8 = lane >> 3, lr = lane & 7;
        #pragma unroll
        for (int mt = 0; mt < 4; mt++) {
            u32 r = (u32)(mt * 16 + (t8 & 1) * 8 + lr);
            aHi[mt] = sptr(Ahi) + r * RB + (u32)((t8 >> 1) * 16);
            aLo[mt] = aHi[mt] + (SA_LO - SA_HI);
        }
    }

    float D[4][4][4];
    float hold[4][4];
    #pragma unroll
    for (int mt = 0; mt < 4; mt++)
        #pragma unroll
        for (int j = 0; j < 4; j++) hold[mt][j] = 0.0f;

    // =========================== ENCODER ===========================
    for (int t = 0; t < SEQ; t++) {
        float xv[8];
        const bool pf = (tid < ROWS) && (t + 1 < SEQ);
        if (pf) {
            const float4* p = (const float4*)(x + ((size_t)(t + 1) * BATCH + rowb + tid) * 8);
            float4 a = p[0], b = p[1];
            xv[0]=a.x; xv[1]=a.y; xv[2]=a.z; xv[3]=a.w; xv[4]=b.x; xv[5]=b.y; xv[6]=b.z; xv[7]=b.w;
        }
        gemm_step(aHi, aLo, Bh, Bl, D);
        __syncthreads();                       // all warps done reading A
        epi(Ahi, Alo, warp, lane, D, hold);    // write h_{t+1}
        if (pf) stage_x(Ahi, Alo, tid, xv);
        __syncthreads();                       // A ready
    }

    // ---- phase swap: decoder B fragments + xy[0] ----
    build_B(Bs, dWih, dWhh, dbih, dbhh, 0, tid);  __syncthreads();
    load_frags(Bs, warp, lane, Bh);               __syncthreads();
    build_B(Bs, dWih, dWhh, dbih, dbhh, 1, tid);  __syncthreads();
    load_frags(Bs, warp, lane, Bl);
    if (tid < ROWS) {
        const float4* p = (const float4*)(xy + ((size_t)rowb + tid) * 8);
        float4 a = p[0], b = p[1];
        float v[8] = {a.x, a.y, a.z, a.w, b.x, b.y, b.z, b.w};
        stage_x(Ahi, Alo, tid, v);
    }
    __syncthreads();

    // =========================== DECODER ===========================
    for (int t = 0; t < LAB; t++) {
        gemm_step(aHi, aLo, Bh, Bl, D);
        __syncthreads();
        epi(Ahi, Alo, warp, lane, D, hold);
        __syncthreads();                       // h_{t+1} visible in A

        if (tid < ROWS) {                      // out-projection for row = tid
            float acc[8];
            #pragma unroll
            for (int o = 0; o < 8; o++) acc[o] = bo[o];
            const half2* rh = (const half2*)(Ahi + tid * KP);
            const half2* rl = (const half2*)(Alo + tid * KP);
            #pragma unroll 8
            for (int k2 = 0; k2 < 32; k2++) {
                float2 hq = __half22float2(rh[k2]);
                float2 lq = __half22float2(rl[k2]);
                float h0 = hq.x + lq.x, h1 = hq.y + lq.y;
                const float* w0 = wo + (2 * k2) * 8;
                const float* w1 = w0 + 8;
                #pragma unroll
                for (int o = 0; o < 8; o++)
                    acc[o] = fmaf(h0, w0[o], fmaf(h1, w1[o], acc[o]));
            }
            float* og = out + ((size_t)t * BATCH + rowb + tid) * 8;
            *(float4*)og       = make_float4(acc[0], acc[1], acc[2], acc[3]);
            *((float4*)og + 1) = make_float4(acc[4], acc[5], acc[6], acc[7]);
            stage_x(Ahi, Alo, tid, acc);       // autoregressive feedback
        }
        __syncthreads();
    }
}

extern "C" void kernel_launch(void* const* d_in, const int* in_sizes, int n_in,
                              void* d_out, int out_size) {
    (void)in_sizes; (void)n_in; (void)out_size;
    cudaFuncSetAttribute(seq2seq_mma_kernel,
                         cudaFuncAttributeMaxDynamicSharedMemorySize, STOT);
    seq2seq_mma_kernel<<<NBLK, NTHR, STOT>>>(
        (const float*)d_in[0], (const float*)d_in[1],
        (const float*)d_in[2], (const float*)d_in[3],
        (const float*)d_in[4], (const float*)d_in[5],
        (const float*)d_in[6], (const float*)d_in[7],
        (const float*)d_in[8], (const float*)d_in[9],
        (const float*)d_in[10], (const float*)d_in[11],
        (float*)d_out);
}

// round 11
// speedup vs baseline: 2.4377x; 1.2339x over previous
#include <cuda_runtime.h>
#include <cuda_fp16.h>

typedef unsigned int u32;

#define SEQ   256
#define LAB   128
#define BATCH 8192
#define ROWS  32
#define NBLK  (BATCH / ROWS)   // 256
#define NTHR  256
#define KP    88               // k-stride in fp16 (176B rows: conflict-free ldmatrix)
#define RB    176
#define KC    5                // K=80: 64 h + 8 x + 1 bias + 7 pad

// ---- SMEM byte offsets ----
// A: [2 buf][hi|lo][32][88] fp16.  buf stride 11264, hi->lo +5632
#define SA    0
#define ABUF  11264
#define ALO   5632
#define SB    22528            // B scratch; holds B_lo permanently after init (45056B)
#define SWOUT 67584            // [64][8] f32
#define SBOUT 69632            // [8] f32
#define STOT  69696

static __device__ __forceinline__ u32 sptr(const void* p) {
    return (u32)__cvta_generic_to_shared(p);
}
static __device__ __forceinline__ void ldm4(u32* r, u32 a) {
    asm volatile("ldmatrix.sync.aligned.m8n8.x4.shared.b16 {%0,%1,%2,%3},[%4];"
        : "=r"(r[0]), "=r"(r[1]), "=r"(r[2]), "=r"(r[3]) : "r"(a));
}
static __device__ __forceinline__ void ldm2(u32* r, u32 a) {
    asm volatile("ldmatrix.sync.aligned.m8n8.x2.shared.b16 {%0,%1},[%2];"
        : "=r"(r[0]), "=r"(r[1]) : "r"(a));
}
static __device__ __forceinline__ void mmaop(float* d, const u32* a, const u32* b) {
    asm volatile("mma.sync.aligned.m16n8k16.row.col.f32.f16.f16.f32 "
        "{%0,%1,%2,%3},{%4,%5,%6,%7},{%8,%9},{%0,%1,%2,%3};"
        : "+f"(d[0]), "+f"(d[1]), "+f"(d[2]), "+f"(d[3])
        : "r"(a[0]), "r"(a[1]), "r"(a[2]), "r"(a[3]), "r"(b[0]), "r"(b[1]));
}
static __device__ __forceinline__ float tanha(float x) {
    float y; asm("tanh.approx.f32 %0,%1;" : "=f"(y) : "f"(x)); return y;
}
static __device__ __forceinline__ float sigt(float x) { return fmaf(0.5f, tanha(0.5f * x), 0.5f); }

// B[n][k]: r 0-63, z 64-127, ni 128-191, nh 192-255. k: 0-63 Whh, 64-71 Wih, 72 bias.
static __device__ void build_B(half* Bs,
                               const float* __restrict__ Wih, const float* __restrict__ Whh,
                               const float* __restrict__ bih, const float* __restrict__ bhh,
                               int term, int tid) {
    for (int i = tid; i < 256 * KP; i += NTHR) {
        int n = i / KP, k = i % KP;
        float v = 0.0f;
        if (k < 64) {
            if (n < 128) v = Whh[n * 64 + k];
            else if (n >= 192) v = Whh[(n - 64) * 64 + k];
        } else if (k < 72) {
            if (n < 192) v = Wih[n * 8 + (k - 64)];
        } else if (k == 72) {
            if (n < 128) v = bih[n] + bhh[n];
            else if (n < 192) v = bih[n];
            else v = bhh[n - 64];
        }
        half h = __float2half_rn(v);
        if (term) h = __float2half_rn(v - __half2float(h));
        Bs[i] = h;
    }
}

// Resident hi-fragments: q-tiles {w, w+8, w+24} full K, {w+16} (ni) only kc=4.
static __device__ __forceinline__ void load_hi_frags(u32 fb, int warp,
                                                     u32 Bh[3][KC][2], u32 BhNi[2]) {
    const int qmap[3] = {0, 1, 3};
    #pragma unroll
    for (int qi = 0; qi < 3; qi++) {
        u32 bq = fb + (u32)((warp + 8 * qmap[qi]) * 8 * RB);
        #pragma unroll
        for (int kc = 0; kc < KC; kc++) ldm2(Bh[qi][kc], bq + kc * 32);
    }
    ldm2(BhNi, fb + (u32)((warp + 16) * 8 * RB) + 4 * 32);
}

// One GEMM step: D[2][4][4]; B_lo re-loaded from SMEM per kc.
static __device__ __forceinline__ void gemm_step(u32 aHi0, u32 aHi1,
                                                 const u32 blq[4],
                                                 const u32 Bh[3][KC][2], const u32 BhNi[2],
                                                 float D[2][4][4]) {
    #pragma unroll
    for (int mt = 0; mt < 2; mt++)
        #pragma unroll
        for (int q = 0; q < 4; q++)
            #pragma unroll
            for (int e = 0; e < 4; e++) D[mt][q][e] = 0.0f;
    #pragma unroll
    for (int kc = 0; kc < KC; kc++) {
        u32 ah[2][4], al[2][4];
        ldm4(ah[0], aHi0 + kc * 32);
        ldm4(ah[1], aHi1 + kc * 32);
        ldm4(al[0], aHi0 + ALO + kc * 32);
        ldm4(al[1], aHi1 + ALO + kc * 32);
        u32 blr[2], blz[2], blnh[2];
        ldm2(blr,  blq[0] + kc * 32);
        ldm2(blz,  blq[1] + kc * 32);
        ldm2(blnh, blq[3] + kc * 32);
        #pragma unroll
        for (int mt = 0; mt < 2; mt++) {
            mmaop(D[mt][0], ah[mt], Bh[0][kc]);
            mmaop(D[mt][0], al[mt], Bh[0][kc]);
            mmaop(D[mt][0], ah[mt], blr);
            mmaop(D[mt][1], ah[mt], Bh[1][kc]);
            mmaop(D[mt][1], al[mt], Bh[1][kc]);
            mmaop(D[mt][1], ah[mt], blz);
            mmaop(D[mt][3], ah[mt], Bh[2][kc]);
            mmaop(D[mt][3], al[mt], Bh[2][kc]);
            mmaop(D[mt][3], ah[mt], blnh);
        }
        if (kc == 4) {
            u32 blni[2];
            ldm2(blni, blq[2] + 4 * 32);
            #pragma unroll
            for (int mt = 0; mt < 2; mt++) {
                mmaop(D[mt][2], ah[mt], BhNi);
                mmaop(D[mt][2], al[mt], BhNi);
                mmaop(D[mt][2], ah[mt], blni);
            }
        }
    }
}

// Gates in regs; write h' (hi/lo) into next A buffer.
static __device__ __forceinline__ void epi(half* AhiN, half* AloN, int warp, int lane,
                                           float D[2][4][4], float hold[2][4]) {
    const int r0 = lane >> 2;
    const int c0 = warp * 8 + 2 * (lane & 3);
    #pragma unroll
    for (int mt = 0; mt < 2; mt++) {
        float h[4];
        #pragma unroll
        for (int j = 0; j < 4; j++) {
            float R = sigt(D[mt][0][j]);
            float Z = sigt(D[mt][1][j]);
            float N = tanha(fmaf(R, D[mt][3][j], D[mt][2][j]));
            h[j] = fmaf(Z, hold[mt][j] - N, N);
            hold[mt][j] = h[j];
        }
        int ra = mt * 16 + r0, rb = ra + 8;
        half2 h2a = __floats2half2_rn(h[0], h[1]);
        half2 l2a = __floats2half2_rn(h[0] - __low2float(h2a), h[1] - __high2float(h2a));
        half2 h2b = __floats2half2_rn(h[2], h[3]);
        half2 l2b = __floats2half2_rn(h[2] - __low2float(h2b), h[3] - __high2float(h2b));
        *(half2*)(AhiN + ra * KP + c0) = h2a;
        *(half2*)(AloN + ra * KP + c0) = l2a;
        *(half2*)(AhiN + rb * KP + c0) = h2b;
        *(half2*)(AloN + rb * KP + c0) = l2b;
    }
}

static __device__ __forceinline__ void stage_x(half* Ahi, half* Alo, int row, const float* v) {
    #pragma unroll
    for (int j = 0; j < 4; j++) {
        float a = v[2 * j], b = v[2 * j + 1];
        half2 h2 = __floats2half2_rn(a, b);
        half2 l2 = __floats2half2_rn(a - __low2float(h2), b - __high2float(h2));
        *(half2*)(Ahi + row * KP + 64 + 2 * j) = h2;
        *(half2*)(Alo + row * KP + 64 + 2 * j) = l2;
    }
}

__global__ __launch_bounds__(NTHR, 2)
void seq2seq_mma_kernel(const float* __restrict__ x,
                        const float* __restrict__ xy,
                        const float* __restrict__ eWih, const float* __restrict__ eWhh,
                        const float* __restrict__ ebih, const float* __restrict__ ebhh,
                        const float* __restrict__ dWih, const float* __restrict__ dWhh,
                        const float* __restrict__ dbih, const float* __restrict__ dbhh,
                        const float* __restrict__ Wout, const float* __restrict__ bout,
                        float* __restrict__ out)
{
    extern __shared__ char smem[];
    half*  Bs = (half*)(smem + SB);
    float* wo = (float*)(smem + SWOUT);
    float* bo = (float*)(smem + SBOUT);

    const int tid  = threadIdx.x;
    const int lane = tid & 31;
    const int warp = tid >> 5;
    const int rowb = blockIdx.x * ROWS;

    // ---- zero both A buffers, load wout/bout ----
    for (int i = tid * 16; i < SB; i += NTHR * 16) *(uint4*)(smem + i) = make_uint4(0, 0, 0, 0);
    for (int i = tid; i < 512; i += NTHR) { int k = i >> 3, o = i & 7; wo[i] = Wout[o * 64 + k]; }
    if (tid < 8) bo[tid] = bout[tid];
    __syncthreads();
    if (tid < ROWS) {
        ((half*)(smem + SA))[tid * KP + 72]        = __float2half(1.0f);   // bias lane buf0
        ((half*)(smem + SA + ABUF))[tid * KP + 72] = __float2half(1.0f);   // buf1
        const float4* p = (const float4*)(x + ((size_t)rowb + tid) * 8);
        float4 a = p[0], b = p[1];
        float v[8] = {a.x, a.y, a.z, a.w, b.x, b.y, b.z, b.w};
        stage_x((half*)(smem + SA), (half*)(smem + SA + ALO), tid, v);     // x[0] -> buf0
    }
    __syncthreads();

    // ---- encoder B: hi -> frags; lo stays resident in SMEM ----
    u32 Bh[3][KC][2], BhNi[2];
    const u32 fb = sptr(Bs) + (u32)((lane & 7) * RB + ((lane >> 3) & 1) * 16);
    u32 blq[4];
    #pragma unroll
    for (int q = 0; q < 4; q++) blq[q] = fb + (u32)((warp + 8 * q) * 8 * RB);

    build_B(Bs, eWih, eWhh, ebih, ebhh, 0, tid);  __syncthreads();
    load_hi_frags(fb, warp, Bh, BhNi);            __syncthreads();
    build_B(Bs, eWih, eWhh, ebih, ebhh, 1, tid);  __syncthreads();

    // A fragment offsets (within a buffer)
    u32 aoff0, aoff1;
    {
        int t8 = lane >> 3, lr = lane & 7;
        aoff0 = (u32)((0 * 16 + (t8 & 1) * 8 + lr) * RB + (t8 >> 1) * 16);
        aoff1 = (u32)((1 * 16 + (t8 & 1) * 8 + lr) * RB + (t8 >> 1) * 16);
    }
    const u32 sbA = sptr(smem + SA);

    float D[2][4][4];
    float hold[2][4];
    #pragma unroll
    for (int mt = 0; mt < 2; mt++)
        #pragma unroll
        for (int j = 0; j < 4; j++) hold[mt][j] = 0.0f;

    int b = 0;

    // =========================== ENCODER (1 sync/step) ===========================
    for (int t = 0; t < SEQ; t++) {
        float xv[8];
        const bool pf = (tid < ROWS) && (t + 1 < SEQ);
        if (pf) {
            const float4* p = (const float4*)(x + ((size_t)(t + 1) * BATCH + rowb + tid) * 8);
            float4 a = p[0], c = p[1];
            xv[0]=a.x; xv[1]=a.y; xv[2]=a.z; xv[3]=a.w; xv[4]=c.x; xv[5]=c.y; xv[6]=c.z; xv[7]=c.w;
        }
        u32 ab = sbA + (u32)(b * ABUF);
        gemm_step(ab + aoff0, ab + aoff1, blq, Bh, BhNi, D);
        int nb = b ^ 1;
        half* AhiN = (half*)(smem + SA + nb * ABUF);
        half* AloN = AhiN + ALO / 2;
        epi(AhiN, AloN, warp, lane, D, hold);          // writes buf nb (others read buf b)
        if (pf) stage_x(AhiN, AloN, tid, xv);
        __syncthreads();                               // buf nb complete
        b = nb;
    }

    // ---- phase swap: decoder B + xy[0] ---- (b == 0, h_enc in buf0)
    build_B(Bs, dWih, dWhh, dbih, dbhh, 0, tid);  __syncthreads();
    load_hi_frags(fb, warp, Bh, BhNi);            __syncthreads();
    build_B(Bs, dWih, dWhh, dbih, dbhh, 1, tid);
    if (tid < ROWS) {
        const float4* p = (const float4*)(xy + ((size_t)rowb + tid) * 8);
        float4 a = p[0], c = p[1];
        float v[8] = {a.x, a.y, a.z, a.w, c.x, c.y, c.z, c.w};
        stage_x((half*)(smem + SA), (half*)(smem + SA + ALO), tid, v);
    }
    __syncthreads();

    // =========================== DECODER ===========================
    const int orow = tid >> 3;     // 0..31
    const int oo   = tid & 7;
    const float bop = bo[oo];

    for (int t = 0; t < LAB; t++) {
        u32 ab = sbA + (u32)(b * ABUF);
        gemm_step(ab + aoff0, ab + aoff1, blq, Bh, BhNi, D);
        int nb = b ^ 1;
        half* AhiN = (half*)(smem + SA + nb * ABUF);
        half* AloN = AhiN + ALO / 2;
        epi(AhiN, AloN, warp, lane, D, hold);
        __syncthreads();                               // full h' visible

        // out-proj: thread (orow, oo): one output scalar
        {
            float acc = bop;
            const half2* rh = (const half2*)(AhiN + orow * KP);
            const half2* rl = (const half2*)(AloN + orow * KP);
            #pragma unroll 8
            for (int k2 = 0; k2 < 32; k2++) {
                float2 hq = __half22float2(rh[k2]);
                float2 lq = __half22float2(rl[k2]);
                acc = fmaf(hq.x + lq.x, wo[(2 * k2) * 8 + oo],
                      fmaf(hq.y + lq.y, wo[(2 * k2 + 1) * 8 + oo], acc));
            }
            out[((size_t)t * BATCH + rowb + orow) * 8 + oo] = acc;
            if (t + 1 < LAB) {                          // feedback x
                half hh = __float2half_rn(acc);
                AhiN[orow * KP + 64 + oo] = hh;
                AloN[orow * KP + 64 + oo] = __float2half_rn(acc - __half2float(hh));
            }
        }
        __syncthreads();                               // feedback visible
        b = nb;
    }
}

extern "C" void kernel_launch(void* const* d_in, const int* in_sizes, int n_in,
                              void* d_out, int out_size) {
    (void)in_sizes; (void)n_in; (void)out_size;
    cudaFuncSetAttribute(seq2seq_mma_kernel,
                         cudaFuncAttributeMaxDynamicSharedMemorySize, STOT);
    seq2seq_mma_kernel<<<NBLK, NTHR, STOT>>>(
        (const float*)d_in[0], (const float*)d_in[1],
        (const float*)d_in[2], (const float*)d_in[3],
        (const float*)d_in[4], (const float*)d_in[5],
        (const float*)d_in[6], (const float*)d_in[7],
        (const float*)d_in[8], (const float*)d_in[9],
        (const float*)d_in[10], (const float*)d_in[11],
        (float*)d_out);
}